// round 14
// baseline (speedup 1.0000x reference)
#include <cuda_runtime.h>
#include <cuda_bf16.h>
#include <cstdint>

#define BATCH 8
#define CDIM  64
#define NPTS  4096
#define KNBR  16
#define COUT  64
#define KSUP  24          // candidate superset per row PER HALF
#define KTOT  48          // total candidates per row (2 halves)
#define LSTR  26          // smem list row stride (words, EVEN: keeps LDS.64 aligned)
#define NC    64          // candidates per tile in phase B
#define NHALF 2048        // candidates per block (half of NPTS)
#define NTIL  (NHALF / NC) // 32 tiles per block
#define COFF  512.0f      // row-order-preserving positive offset

typedef unsigned long long ull;

// ---------------- scratch (no allocations allowed) ----------------
__device__ float          g_sq  [BATCH * NPTS];
__device__ float          g_sqC [BATCH * NPTS];          // sq + COFF
__device__ int            g_idx [BATCH * NPTS * KNBR];
__device__ float          g_A   [BATCH * NPTS * COUT];
__device__ float          g_Cp  [BATCH * NPTS * COUT];
__device__ float          g_xt  [BATCH * NPTS * CDIM];   // point-major fp32
__device__ __nv_bfloat16  g_xh  [BATCH * NPTS * CDIM];   // point-major bf16
__device__ short          g_cand[BATCH * NPTS * KTOT];

// ---------------- helpers ----------------
__device__ __forceinline__ uint32_t smem_u32(const void* p) {
    uint32_t a;
    asm("{ .reg .u64 t; cvta.to.shared.u64 t, %1; cvt.u32.u64 %0, t; }" : "=r"(a) : "l"(p));
    return a;
}
__device__ __forceinline__ unsigned fsort(float v) {
    unsigned u = __float_as_uint(v);
    return u ^ (0x80000000u | (unsigned)((int)u >> 31));
}
__device__ __forceinline__ void ldmx4(uint32_t* r, uint32_t addr) {
    asm volatile("ldmatrix.sync.aligned.m8n8.x4.shared.b16 {%0,%1,%2,%3}, [%4];"
                 : "=r"(r[0]), "=r"(r[1]), "=r"(r[2]), "=r"(r[3]) : "r"(addr));
}
__device__ __forceinline__ void mma16816(float* c, const uint32_t* a, uint32_t b0, uint32_t b1) {
    asm volatile("mma.sync.aligned.m16n8k16.row.col.f32.bf16.bf16.f32 "
                 "{%0,%1,%2,%3}, {%4,%5,%6,%7}, {%8,%9}, {%0,%1,%2,%3};"
                 : "+f"(c[0]), "+f"(c[1]), "+f"(c[2]), "+f"(c[3])
                 : "r"(a[0]), "r"(a[1]), "r"(a[2]), "r"(a[3]), "r"(b0), "r"(b1));
}
// swizzled byte offset of 16B granule g (0..7) in row rr of a [rows][64bf16] tile
__device__ __forceinline__ int swz(int rr, int g) {
    return rr * 128 + ((g ^ (rr & 7)) << 4);
}
// bitonic compare-and-swap with cross-lane partner (element index bit j == lane bit j)
__device__ __forceinline__ void cas_x(ull& key, int j, bool up, int lane) {
    ull other = __shfl_xor_sync(0xffffffffu, key, j);
    bool low  = (lane & j) == 0;
    bool keep_small = (low == up);
    ull mn = key < other ? key : other;
    ull mx = key < other ? other : key;
    key = keep_small ? mn : mx;
}

// ---------------- kernel 1: squared norms (exact fp32) ----------------
__global__ void sq_kernel(const float* __restrict__ x) {
    int b = blockIdx.y;
    int n = blockIdx.x * blockDim.x + threadIdx.x;
    const float* xp = x + (size_t)b * CDIM * NPTS + n;
    float s = 0.f;
#pragma unroll
    for (int c = 0; c < CDIM; ++c) { float v = xp[c * NPTS]; s = fmaf(v, v, s); }
    g_sq [b * NPTS + n] = s;
    g_sqC[b * NPTS + n] = s + COFF;
}

// ---------------- kernel 1b: transpose to point-major fp32 + bf16 ----------------
__global__ void tr_kernel(const float* __restrict__ x) {
    __shared__ float tile[32][33];
    const int tx = threadIdx.x, ty = threadIdx.y;
    const int n0 = blockIdx.x * 32, c0 = blockIdx.y * 32, b = blockIdx.z;
    const float* xb = x + (size_t)b * CDIM * NPTS;
#pragma unroll
    for (int i = 0; i < 4; ++i)
        tile[ty + i * 8][tx] = xb[(c0 + ty + i * 8) * NPTS + n0 + tx];
    __syncthreads();
#pragma unroll
    for (int i = 0; i < 4; ++i) {
        int n = n0 + ty + i * 8, c = c0 + tx;
        float v = tile[tx][ty + i * 8];
        size_t o = ((size_t)b * NPTS + n) * CDIM + c;
        g_xt[o] = v;
        g_xh[o] = __float2bfloat16(v);
    }
}

// ---------------- kernel 2: HMMA approx distances + per-half top-24 ----------------
// Grid x = (tile, half): each block scans 2048 candidates for 128 rows.
// Keys: raw fp32 bits of v = sqC[m] - 2*dot (> 0, per-row order == d^2 order).
// key = (bits & 0xFFFFF000) | idx12. Single B buffer; warps 4-7 stage B(t+1)
// through registers across the flush barrier. 3 blocks/SM capable.
#define SM_A    0                            // 16384
#define SM_B0   16384                        // 8192
#define SM_SQ   24576                        // float[64] = 256
#define SM_THR  24832                        // float[128] = 512
#define SM_CNT  25344                        // int[4][128] = 2048
#define SM_PEND 27392                        // u32[4][16][128] = 32768
#define SM_LIST 60160                        // u32[128][LSTR] = 13312
#define KNN_SMEM (SM_LIST + 128 * LSTR * 4)  // 73472

__global__ __launch_bounds__(256, 3) void knn_mma_kernel() {
    extern __shared__ char sm[];
    float*    sqb  = (float*)   (sm + SM_SQ);
    float*    thr  = (float*)   (sm + SM_THR);
    int*      cnt  = (int*)     (sm + SM_CNT);
    unsigned* pend = (unsigned*)(sm + SM_PEND);
    unsigned* list = (unsigned*)(sm + SM_LIST);

    const int tid  = threadIdx.x;
    const int w    = tid >> 5;
    const int lane = tid & 31;
    const int b    = blockIdx.y;
    const int half = blockIdx.x & 1;
    const int row0 = (blockIdx.x >> 1) * 128;
    const int cb   = half * NHALF;           // candidate base
    const uint32_t smb = smem_u32(sm);

    const __nv_bfloat16* gb = g_xh + (size_t)b * NPTS * CDIM;

    // prologue: A tile (swizzled), B tile 0, sqC slice 0, thr, list init
#pragma unroll
    for (int i = 0; i < 4; ++i) {    // A: 1024 uint4
        int q = tid + i * 256, rr = q >> 3, g = q & 7;
        *(uint4*)(sm + SM_A + swz(rr, g)) = *(const uint4*)(gb + (size_t)(row0 + rr) * CDIM + g * 8);
    }
#pragma unroll
    for (int i = 0; i < 2; ++i) {    // B0: 512 uint4 (64 rows)
        int q = tid + i * 256, rr = q >> 3, g = q & 7;
        *(uint4*)(sm + SM_B0 + swz(rr, g)) = *(const uint4*)(gb + (size_t)(cb + rr) * CDIM + g * 8);
    }
    if (tid < 16)
        *(float4*)(sqb + tid * 4) = *(const float4*)(g_sqC + (size_t)b * NPTS + cb + tid * 4);
    if (tid < 128) thr[tid] = 3.4e38f;
    for (int i = tid; i < 128 * LSTR; i += 256) list[i] = 0xFFFFFFFFu;
    __syncthreads();

    // GEMM role (all 8 warps): rows wrow..wrow+15
    const int wrow = w * 16;
    const int arow = wrow + (lane & 7) + ((lane >> 3) & 1) * 8;
    const int rA   = wrow + (lane >> 2);
    const int rB   = rA + 8;
    const int seg  = lane & 3;
    const int mloc = seg * 2;
    const int t2   = tid - 128;

    // A fragments: block-constant, load once
    uint32_t af[4][4];
#pragma unroll
    for (int kc = 0; kc < 4; ++kc) {
        int ach = kc * 2 + (lane >> 4);
        ldmx4(af[kc], smb + SM_A + swz(arow, ach));
    }

    // selection state (threads 0..127 own row = row0 + tid); list in smem
    unsigned worstm = 0xFFFFFFFFu;   // slot-mangled max of list (top-27 bits valid)
    int wpos = 0;

    for (int t = 0; t < NTIL; ++t) {
        const float thrA = thr[rA];
        const float thrB = thr[rB];
        const int   tb   = cb + t * NC;
        int cA = 0, cB = 0;   // register counters; <=16 by construction

#pragma unroll
        for (int nf = 0; nf < 8; ++nf) {
            int brow = nf * 8 + (lane & 7);
            int bg   = lane >> 3;
            uint32_t p[4], q4[4];
            ldmx4(p,  smb + SM_B0 + swz(brow, bg));
            ldmx4(q4, smb + SM_B0 + swz(brow, bg + 4));
            float acc[4] = {0.f, 0.f, 0.f, 0.f};
            mma16816(acc, af[0], p[0],  p[1]);
            mma16816(acc, af[1], p[2],  p[3]);
            mma16816(acc, af[2], q4[0], q4[1]);
            mma16816(acc, af[3], q4[2], q4[3]);

            // fused epilogue: v = sqC[m] - 2*dot  (>0; per-row order == d^2)
            int    ml = mloc + nf * 8;
            float2 ss = *(const float2*)(sqb + ml);
            int    m0 = tb + ml;
            float v00 = fmaf(-2.f, acc[0], ss.x);
            float v01 = fmaf(-2.f, acc[1], ss.y);
            float v10 = fmaf(-2.f, acc[2], ss.x);
            float v11 = fmaf(-2.f, acc[3], ss.y);
            if (v00 <= thrA) pend[(seg * 16 + cA++) * 128 + rA] = (__float_as_uint(v00) & 0xFFFFF000u) | (unsigned)m0;
            if (v01 <= thrA) pend[(seg * 16 + cA++) * 128 + rA] = (__float_as_uint(v01) & 0xFFFFF000u) | (unsigned)(m0 + 1);
            if (v10 <= thrB) pend[(seg * 16 + cB++) * 128 + rB] = (__float_as_uint(v10) & 0xFFFFF000u) | (unsigned)m0;
            if (v11 <= thrB) pend[(seg * 16 + cB++) * 128 + rB] = (__float_as_uint(v11) & 0xFFFFF000u) | (unsigned)(m0 + 1);
        }
        cnt[seg * 128 + rA] = cA;
        cnt[seg * 128 + rB] = cB;

        // warps 4-7: stage first half of B(t+1) + sqC(t+1) into registers
        uint4 st0, st1; float sqv = 0.f;
        if (tid >= 128 && t + 1 < NTIL) {
            const __nv_bfloat16* src = gb + (size_t)(cb + (t + 1) * NC) * CDIM;
            { int q = t2,       rr = q >> 3, g = q & 7; st0 = *(const uint4*)(src + (size_t)rr * CDIM + g * 8); }
            { int q = t2 + 128, rr = q >> 3, g = q & 7; st1 = *(const uint4*)(src + (size_t)rr * CDIM + g * 8); }
            if (t2 < 64) sqv = g_sqC[(size_t)b * NPTS + cb + (t + 1) * NC + t2];
        }
        __syncthreads();   // pend + cnt visible; B(t) fully consumed

        if (tid < 128) {
            unsigned* lrow = list + tid * LSTR;
#pragma unroll
            for (int sg = 0; sg < 4; ++sg) {
                unsigned myc  = (unsigned)cnt[sg * 128 + tid];
                unsigned cmax = __reduce_max_sync(0xffffffffu, myc);
                for (unsigned j = 0; j < cmax; ++j) {
                    unsigned kn = (j < myc) ? pend[(sg * 16 + (int)j) * 128 + tid] : 0xFFFFFFFFu;
                    bool take = kn < worstm;
                    if (__any_sync(0xffffffffu, take)) {
                        if (take) lrow[wpos] = kn;           // 1 STS, dynamic slot
                        // rescan: slot-packed max via IMNMX
                        unsigned m = 0;
#pragma unroll
                        for (int s = 0; s < KSUP; s += 2) {
                            uint2 two = *(const uint2*)(lrow + s);
                            unsigned t0 = (two.x & 0xFFFFFFE0u) | (unsigned)s;
                            unsigned t1 = (two.y & 0xFFFFFFE0u) | (unsigned)(s + 1);
                            unsigned mx = t0 > t1 ? t0 : t1;
                            m = m > mx ? m : mx;
                        }
                        worstm = m;
                        wpos = (int)(m & 31u);
                    }
                }
            }
            thr[tid] = __uint_as_float(worstm | 0xFFFu);
        } else if (t + 1 < NTIL) {
            // warps 4-7: store staged half, then load+store second half
            const __nv_bfloat16* src = gb + (size_t)(cb + (t + 1) * NC) * CDIM;
            { int q = t2,       rr = q >> 3, g = q & 7; *(uint4*)(sm + SM_B0 + swz(rr, g)) = st0; }
            { int q = t2 + 128, rr = q >> 3, g = q & 7; *(uint4*)(sm + SM_B0 + swz(rr, g)) = st1; }
            { int q = t2 + 256, rr = q >> 3, g = q & 7;
              *(uint4*)(sm + SM_B0 + swz(rr, g)) = *(const uint4*)(src + (size_t)rr * CDIM + g * 8); }
            { int q = t2 + 384, rr = q >> 3, g = q & 7;
              *(uint4*)(sm + SM_B0 + swz(rr, g)) = *(const uint4*)(src + (size_t)rr * CDIM + g * 8); }
            if (t2 < 64) sqb[t2] = sqv;
        }
        __syncthreads();   // flush done (thr updated), B(t+1) ready, pend reusable
    }

    if (tid < 128) {
        short* op = g_cand + ((size_t)b * NPTS + row0 + tid) * KTOT + half * KSUP;
        const unsigned* lrow = list + tid * LSTR;
#pragma unroll
        for (int k = 0; k < KSUP; ++k) op[k] = (short)(lrow[k] & 0xFFFu);
    }
}

// ---------------- kernel 2b: exact rescore of 48 candidates, top-16 ----------------
// 64-element bitonic sort, 2 keys/lane (elements: lane and lane+32).
__global__ __launch_bounds__(256) void rescore_kernel() {
    __shared__ float xrow[8][CDIM];
    __shared__ float dots[8][KTOT];
    const int lane = threadIdx.x & 31;
    const int w    = threadIdx.x >> 5;
    const int b    = blockIdx.y;
    const int n    = blockIdx.x * 8 + w;
    const size_t rb = (size_t)b * NPTS + n;

    *(float2*)(&xrow[w][lane * 2]) = *(const float2*)(g_xt + rb * CDIM + lane * 2);
    __syncwarp();

    const short* cp = g_cand + rb * KTOT;
    const float* xseg = &xrow[w][(lane & 3) * 16];

    // 6 groups of 8 candidates; 4 lanes per candidate (coalesced 256B rows)
#pragma unroll
    for (int g = 0; g < 6; ++g) {
        int c = g * 8 + (lane >> 2);
        int j = (int)cp[c];
        const float* yp = g_xt + ((size_t)b * NPTS + j) * CDIM + (lane & 3) * 16;
        float d = 0.f;
#pragma unroll
        for (int q = 0; q < 4; ++q) {
            float4 yv = *(const float4*)(yp + q * 4);
            float4 xv = *(const float4*)(xseg + q * 4);
            d = fmaf(xv.x, yv.x, d);
            d = fmaf(xv.y, yv.y, d);
            d = fmaf(xv.z, yv.z, d);
            d = fmaf(xv.w, yv.w, d);
        }
        d += __shfl_xor_sync(0xffffffffu, d, 1);
        d += __shfl_xor_sync(0xffffffffu, d, 2);
        if ((lane & 3) == 0) dots[w][c] = d;
    }
    __syncwarp();

    // keys: element lane -> candidate lane; element lane+32 -> candidate lane+32 (lane<16)
    ull key0, key1 = ~0ULL;
    {
        int j = (int)cp[lane];
        if (j == n) key0 = ~0ULL;
        else {
            float dist = fmaf(-2.f, dots[w][lane], g_sq[(size_t)b * NPTS + j]);
            key0 = ((ull)fsort(dist) << 32) | (unsigned)j;
        }
    }
    if (lane < 16) {
        int j = (int)cp[lane + 32];
        if (j != n) {
            float dist = fmaf(-2.f, dots[w][lane + 32], g_sq[(size_t)b * NPTS + j]);
            key1 = ((ull)fsort(dist) << 32) | (unsigned)j;
        }
    }

    // bitonic sort of 64 elements (ascending)
#pragma unroll
    for (int k = 2; k <= 32; k <<= 1) {
        bool up0 = true, up1 = true;
#pragma unroll
        for (int j = 16; j >= 1; j >>= 1) {
            if (j >= k) continue;           // schedule j = k/2 .. 1
            // direction per element: (e & k) == 0
            up0 = ((lane & k) == 0);
            up1 = (k == 32) ? false : up0;  // ((lane+32)&32) != 0
            cas_x(key0, j, up0, lane);
            cas_x(key1, j, up1, lane);
        }
    }
    // k = 64 merge: j=32 is intra-lane (e=lane vs e=lane+32), then j=16..1 all ascending
    {
        ull mn = key0 < key1 ? key0 : key1;
        ull mx = key0 < key1 ? key1 : key0;
        key0 = mn; key1 = mx;
#pragma unroll
        for (int j = 16; j >= 1; j >>= 1) {
            cas_x(key0, j, true, lane);
            cas_x(key1, j, true, lane);
        }
    }

    if (lane < KNBR)
        g_idx[rb * KNBR + lane] = (int)(key0 & 0xFFFFu);
}

// ---------------- kernel 3: A = W1.x ; Cpre = (W2-W1).x + b1+b2 ----------------
__global__ void feat_kernel(const float* __restrict__ x,
                            const float* __restrict__ W1, const float* __restrict__ b1,
                            const float* __restrict__ W2, const float* __restrict__ b2) {
    __shared__ float xs [CDIM][64];
    __shared__ float w1s[COUT][CDIM];
    __shared__ float wds[COUT][CDIM];
    __shared__ float bs [COUT];

    const int tid = threadIdx.x;
    const int b   = blockIdx.y;
    const int n0  = blockIdx.x * 64;
    const float* xb = x + (size_t)b * CDIM * NPTS;

#pragma unroll
    for (int i = 0; i < 4; ++i) {
        int q = tid + i * 256, c = q >> 4, mg = q & 15;
        *(float4*)(&xs[c][mg * 4]) = *(const float4*)(xb + c * NPTS + n0 + mg * 4);
    }
#pragma unroll
    for (int i = 0; i < 4; ++i) {
        int q = tid + i * 256, o = q >> 4, cg = (q & 15) * 4;
        float4 w1v = *(const float4*)(W1 + o * CDIM + cg);
        float4 w2v = *(const float4*)(W2 + o * CDIM + cg);
        *(float4*)(&w1s[o][cg]) = w1v;
        *(float4*)(&wds[o][cg]) = make_float4(w2v.x - w1v.x, w2v.y - w1v.y,
                                              w2v.z - w1v.z, w2v.w - w1v.w);
    }
    if (tid < COUT) bs[tid] = b1[tid] + b2[tid];
    __syncthreads();

    const int tx = tid & 15;
    const int ty = tid >> 4;
    float aA[4][4] = {}, aC[4][4] = {};
#pragma unroll 16
    for (int c = 0; c < CDIM; ++c) {
        float4 xv = *(const float4*)(&xs[c][tx * 4]);
        float xr[4] = { xv.x, xv.y, xv.z, xv.w };
#pragma unroll
        for (int jj = 0; jj < 4; ++jj) {
            float w1e = w1s[ty * 4 + jj][c];
            float wde = wds[ty * 4 + jj][c];
#pragma unroll
            for (int i = 0; i < 4; ++i) {
                aA[i][jj] = fmaf(xr[i], w1e, aA[i][jj]);
                aC[i][jj] = fmaf(xr[i], wde, aC[i][jj]);
            }
        }
    }
#pragma unroll
    for (int i = 0; i < 4; ++i) {
        int n = n0 + tx * 4 + i;
        float* ap = g_A  + ((size_t)b * NPTS + n) * COUT + ty * 4;
        float* cp = g_Cp + ((size_t)b * NPTS + n) * COUT + ty * 4;
        *(float4*)ap = make_float4(aA[i][0], aA[i][1], aA[i][2], aA[i][3]);
        *(float4*)cp = make_float4(aC[i][0] + bs[ty * 4 + 0],
                                   aC[i][1] + bs[ty * 4 + 1],
                                   aC[i][2] + bs[ty * 4 + 2],
                                   aC[i][3] + bs[ty * 4 + 3]);
    }
}

// ---------------- kernel 4: gather-max + relu (2 points/thread ILP) ----------------
__global__ __launch_bounds__(256) void gather_kernel(float* __restrict__ out) {
    const int tid = threadIdx.x;
    const int b   = blockIdx.y;
    const int l   = tid & 63;
    const int g   = tid >> 6;
    const int n1  = blockIdx.x * 128 + l;
    const int n2  = n1 + 64;
    const int* ip1 = g_idx + ((size_t)b * NPTS + n1) * KNBR;
    const int* ip2 = g_idx + ((size_t)b * NPTS + n2) * KNBR;

    float mx1[16], mx2[16];
#pragma unroll
    for (int i = 0; i < 16; ++i) { mx1[i] = -3.4e38f; mx2[i] = -3.4e38f; }

#pragma unroll
    for (int k = 0; k < KNBR; ++k) {
        int j1 = ip1[k], j2 = ip2[k];
        const float4* ap1 = (const float4*)(g_A + ((size_t)b * NPTS + j1) * COUT + g * 16);
        const float4* ap2 = (const float4*)(g_A + ((size_t)b * NPTS + j2) * COUT + g * 16);
#pragma unroll
        for (int q = 0; q < 4; ++q) {
            float4 v1 = ap1[q];
            float4 v2 = ap2[q];
            mx1[q * 4 + 0] = fmaxf(mx1[q * 4 + 0], v1.x);
            mx1[q * 4 + 1] = fmaxf(mx1[q * 4 + 1], v1.y);
            mx1[q * 4 + 2] = fmaxf(mx1[q * 4 + 2], v1.z);
            mx1[q * 4 + 3] = fmaxf(mx1[q * 4 + 3], v1.w);
            mx2[q * 4 + 0] = fmaxf(mx2[q * 4 + 0], v2.x);
            mx2[q * 4 + 1] = fmaxf(mx2[q * 4 + 1], v2.y);
            mx2[q * 4 + 2] = fmaxf(mx2[q * 4 + 2], v2.z);
            mx2[q * 4 + 3] = fmaxf(mx2[q * 4 + 3], v2.w);
        }
    }
    const float4* cp1 = (const float4*)(g_Cp + ((size_t)b * NPTS + n1) * COUT + g * 16);
    const float4* cp2 = (const float4*)(g_Cp + ((size_t)b * NPTS + n2) * COUT + g * 16);
    float* op1 = out + ((size_t)b * COUT + g * 16) * NPTS + n1;
    float* op2 = out + ((size_t)b * COUT + g * 16) * NPTS + n2;
#pragma unroll
    for (int q = 0; q < 4; ++q) {
        float4 c1 = cp1[q];
        float4 c2 = cp2[q];
        op1[(q * 4 + 0) * NPTS] = fmaxf(c1.x + mx1[q * 4 + 0], 0.f);
        op1[(q * 4 + 1) * NPTS] = fmaxf(c1.y + mx1[q * 4 + 1], 0.f);
        op1[(q * 4 + 2) * NPTS] = fmaxf(c1.z + mx1[q * 4 + 2], 0.f);
        op1[(q * 4 + 3) * NPTS] = fmaxf(c1.w + mx1[q * 4 + 3], 0.f);
        op2[(q * 4 + 0) * NPTS] = fmaxf(c2.x + mx2[q * 4 + 0], 0.f);
        op2[(q * 4 + 1) * NPTS] = fmaxf(c2.y + mx2[q * 4 + 1], 0.f);
        op2[(q * 4 + 2) * NPTS] = fmaxf(c2.z + mx2[q * 4 + 2], 0.f);
        op2[(q * 4 + 3) * NPTS] = fmaxf(c2.w + mx2[q * 4 + 3], 0.f);
    }
}

// ---------------- launch ----------------
extern "C" void kernel_launch(void* const* d_in, const int* in_sizes, int n_in,
                              void* d_out, int out_size) {
    const float *x = nullptr, *W1 = nullptr, *b1 = nullptr, *W2 = nullptr, *b2 = nullptr;
    for (int i = 0; i < n_in; ++i) {
        int s = in_sizes[i];
        const float* p = (const float*)d_in[i];
        if      (s == BATCH * CDIM * NPTS) x = p;
        else if (s == COUT * CDIM)        { if (!W1) W1 = p; else W2 = p; }
        else if (s == COUT)               { if (!b1) b1 = p; else b2 = p; }
    }
    float* out = (float*)d_out;
    (void)out_size;

    cudaFuncSetAttribute(knn_mma_kernel, cudaFuncAttributeMaxDynamicSharedMemorySize, KNN_SMEM);

    // knn placed 4th so the fixed ncu capture slot profiles it
    sq_kernel      <<<dim3(NPTS / 256, BATCH), 256>>>(x);
    tr_kernel      <<<dim3(NPTS / 32, CDIM / 32, BATCH), dim3(32, 8)>>>(x);
    feat_kernel    <<<dim3(NPTS / 64, BATCH), 256>>>(x, W1, b1, W2, b2);
    knn_mma_kernel <<<dim3((NPTS / 128) * 2, BATCH), 256, KNN_SMEM>>>();
    rescore_kernel <<<dim3(NPTS / 8, BATCH), 256>>>();
    gather_kernel  <<<dim3(NPTS / 128, BATCH), 256>>>(out);
}

// round 15
// speedup vs baseline: 1.0737x; 1.0737x over previous
#include <cuda_runtime.h>
#include <cuda_bf16.h>
#include <cstdint>

#define BATCH 8
#define CDIM  64
#define NPTS  4096
#define KNBR  16
#define COUT  64
#define KSUP  24          // candidate superset per row
#define LSTR  26          // smem list row stride (words, EVEN: keeps LDS.64 aligned)
#define ROWS  64          // rows per knn block
#define NC    64          // candidates per tile
#define NTIL  (NPTS / NC) // 64
#define COFF  512.0f      // row-order-preserving positive offset

typedef unsigned long long ull;

// ---------------- scratch (no allocations allowed) ----------------
__device__ float          g_sq  [BATCH * NPTS];
__device__ float          g_sqC [BATCH * NPTS];          // sq + COFF
__device__ int            g_idx [BATCH * NPTS * KNBR];
__device__ float          g_A   [BATCH * NPTS * COUT];
__device__ float          g_Cp  [BATCH * NPTS * COUT];
__device__ float          g_xt  [BATCH * NPTS * CDIM];   // point-major fp32
__device__ __nv_bfloat16  g_xh  [BATCH * NPTS * CDIM];   // point-major bf16
__device__ short          g_cand[BATCH * NPTS * KSUP];

// ---------------- helpers ----------------
__device__ __forceinline__ uint32_t smem_u32(const void* p) {
    uint32_t a;
    asm("{ .reg .u64 t; cvta.to.shared.u64 t, %1; cvt.u32.u64 %0, t; }" : "=r"(a) : "l"(p));
    return a;
}
__device__ __forceinline__ unsigned fsort(float v) {
    unsigned u = __float_as_uint(v);
    return u ^ (0x80000000u | (unsigned)((int)u >> 31));
}
__device__ __forceinline__ void ldmx4(uint32_t* r, uint32_t addr) {
    asm volatile("ldmatrix.sync.aligned.m8n8.x4.shared.b16 {%0,%1,%2,%3}, [%4];"
                 : "=r"(r[0]), "=r"(r[1]), "=r"(r[2]), "=r"(r[3]) : "r"(addr));
}
__device__ __forceinline__ void mma16816(float* c, const uint32_t* a, uint32_t b0, uint32_t b1) {
    asm volatile("mma.sync.aligned.m16n8k16.row.col.f32.bf16.bf16.f32 "
                 "{%0,%1,%2,%3}, {%4,%5,%6,%7}, {%8,%9}, {%0,%1,%2,%3};"
                 : "+f"(c[0]), "+f"(c[1]), "+f"(c[2]), "+f"(c[3])
                 : "r"(a[0]), "r"(a[1]), "r"(a[2]), "r"(a[3]), "r"(b0), "r"(b1));
}
// swizzled byte offset of 16B granule g (0..7) in row rr of a [rows][64bf16] tile
__device__ __forceinline__ int swz(int rr, int g) {
    return rr * 128 + ((g ^ (rr & 7)) << 4);
}

// ---------------- kernel 1: squared norms (exact fp32) ----------------
__global__ void sq_kernel(const float* __restrict__ x) {
    int b = blockIdx.y;
    int n = blockIdx.x * blockDim.x + threadIdx.x;
    const float* xp = x + (size_t)b * CDIM * NPTS + n;
    float s = 0.f;
#pragma unroll
    for (int c = 0; c < CDIM; ++c) { float v = xp[c * NPTS]; s = fmaf(v, v, s); }
    g_sq [b * NPTS + n] = s;
    g_sqC[b * NPTS + n] = s + COFF;
}

// ---------------- kernel 1b: transpose to point-major fp32 + bf16 ----------------
__global__ void tr_kernel(const float* __restrict__ x) {
    __shared__ float tile[32][33];
    const int tx = threadIdx.x, ty = threadIdx.y;
    const int n0 = blockIdx.x * 32, c0 = blockIdx.y * 32, b = blockIdx.z;
    const float* xb = x + (size_t)b * CDIM * NPTS;
#pragma unroll
    for (int i = 0; i < 4; ++i)
        tile[ty + i * 8][tx] = xb[(c0 + ty + i * 8) * NPTS + n0 + tx];
    __syncthreads();
#pragma unroll
    for (int i = 0; i < 4; ++i) {
        int n = n0 + ty + i * 8, c = c0 + tx;
        float v = tile[tx][ty + i * 8];
        size_t o = ((size_t)b * NPTS + n) * CDIM + c;
        g_xt[o] = v;
        g_xh[o] = __float2bfloat16(v);
    }
}

// ---------------- kernel 2: HMMA approx distances + top-24 superset ----------------
// 64 rows per block (grid 512), each block scans ALL 4096 candidates once:
// per-row selection work identical to the 128-row version, 2x grid parallelism.
// Warp (g,h): rows g*16..+16, candidates h*32..+32 of each 64-cand tile.
// Keys: raw fp32 bits of v = sqC[m] - 2*dot (> 0, per-row order == d^2 order).
// key = (bits & 0xFFFFF000) | idx12. Flush = threads 0-63; B(t+1) prefetch by
// warps 2-7 (1 staged uint4 + 2 direct loads under flush). 4 blocks/SM.
#define SM_A    0                            // 8192
#define SM_B0   8192                         // 8192
#define SM_SQ   16384                        // float[64] = 256
#define SM_THR  16640                        // float[64] = 256
#define SM_CNT  16896                        // int[8][64] = 2048
#define SM_PEND 18944                        // u32[8][8][64] = 16384
#define SM_LIST 35328                        // u32[64][LSTR] = 6656
#define KNN_SMEM (SM_LIST + ROWS * LSTR * 4) // 41984

__global__ __launch_bounds__(256, 4) void knn_mma_kernel() {
    extern __shared__ char sm[];
    float*    sqb  = (float*)   (sm + SM_SQ);
    float*    thr  = (float*)   (sm + SM_THR);
    int*      cnt  = (int*)     (sm + SM_CNT);
    unsigned* pend = (unsigned*)(sm + SM_PEND);
    unsigned* list = (unsigned*)(sm + SM_LIST);

    const int tid  = threadIdx.x;
    const int w    = tid >> 5;
    const int lane = tid & 31;
    const int b    = blockIdx.y;
    const int row0 = blockIdx.x * ROWS;
    const uint32_t smb = smem_u32(sm);

    const __nv_bfloat16* gb = g_xh + (size_t)b * NPTS * CDIM;

    // prologue: A tile (swizzled, 64 rows), B tile 0, sqC slice 0, thr, list init
#pragma unroll
    for (int i = 0; i < 2; ++i) {    // A: 512 uint4
        int q = tid + i * 256, rr = q >> 3, g = q & 7;
        *(uint4*)(sm + SM_A + swz(rr, g)) = *(const uint4*)(gb + (size_t)(row0 + rr) * CDIM + g * 8);
    }
#pragma unroll
    for (int i = 0; i < 2; ++i) {    // B0: 512 uint4 (64 rows)
        int q = tid + i * 256, rr = q >> 3, g = q & 7;
        *(uint4*)(sm + SM_B0 + swz(rr, g)) = *(const uint4*)(gb + (size_t)rr * CDIM + g * 8);
    }
    if (tid < 16)
        *(float4*)(sqb + tid * 4) = *(const float4*)(g_sqC + (size_t)b * NPTS + tid * 4);
    if (tid < ROWS) thr[tid] = 3.4e38f;
    for (int i = tid; i < ROWS * LSTR; i += 256) list[i] = 0xFFFFFFFFu;
    __syncthreads();

    // GEMM role: warp w -> row group (w>>1)*16, candidate half (w&1)*32
    const int wrow = (w >> 1) * 16;
    const int wh   = w & 1;
    const int arow = wrow + (lane & 7) + ((lane >> 3) & 1) * 8;
    const int rA   = wrow + (lane >> 2);
    const int rB   = rA + 8;
    const int seg  = wh * 4 + (lane & 3);
    const int mloc = wh * 32 + (lane & 3) * 2;
    const int pid  = tid - 64;                // prefetch id (warps 2-7)

    // A fragments: block-constant, load once
    uint32_t af[4][4];
#pragma unroll
    for (int kc = 0; kc < 4; ++kc) {
        int ach = kc * 2 + (lane >> 4);
        ldmx4(af[kc], smb + SM_A + swz(arow, ach));
    }

    // selection state (threads 0..63 own row = row0 + tid); list in smem
    unsigned worstm = 0xFFFFFFFFu;   // slot-mangled max of list (top-27 bits valid)
    int wpos = 0;

    for (int t = 0; t < NTIL; ++t) {
        const float thrA = thr[rA];
        const float thrB = thr[rB];
        const int   tb   = t * NC;
        int cA = 0, cB = 0;   // register counters; <=8 by construction

#pragma unroll
        for (int nf = 0; nf < 4; ++nf) {
            int brow = wh * 32 + nf * 8 + (lane & 7);
            int bg   = lane >> 3;
            uint32_t p[4], q4[4];
            ldmx4(p,  smb + SM_B0 + swz(brow, bg));
            ldmx4(q4, smb + SM_B0 + swz(brow, bg + 4));
            float acc[4] = {0.f, 0.f, 0.f, 0.f};
            mma16816(acc, af[0], p[0],  p[1]);
            mma16816(acc, af[1], p[2],  p[3]);
            mma16816(acc, af[2], q4[0], q4[1]);
            mma16816(acc, af[3], q4[2], q4[3]);

            // fused epilogue: v = sqC[m] - 2*dot  (>0; per-row order == d^2)
            int    ml = mloc + nf * 8;
            float2 ss = *(const float2*)(sqb + ml);
            int    m0 = tb + ml;
            float v00 = fmaf(-2.f, acc[0], ss.x);
            float v01 = fmaf(-2.f, acc[1], ss.y);
            float v10 = fmaf(-2.f, acc[2], ss.x);
            float v11 = fmaf(-2.f, acc[3], ss.y);
            if (v00 <= thrA) pend[(seg * 8 + cA++) * ROWS + rA] = (__float_as_uint(v00) & 0xFFFFF000u) | (unsigned)m0;
            if (v01 <= thrA) pend[(seg * 8 + cA++) * ROWS + rA] = (__float_as_uint(v01) & 0xFFFFF000u) | (unsigned)(m0 + 1);
            if (v10 <= thrB) pend[(seg * 8 + cB++) * ROWS + rB] = (__float_as_uint(v10) & 0xFFFFF000u) | (unsigned)m0;
            if (v11 <= thrB) pend[(seg * 8 + cB++) * ROWS + rB] = (__float_as_uint(v11) & 0xFFFFF000u) | (unsigned)(m0 + 1);
        }
        cnt[seg * ROWS + rA] = cA;
        cnt[seg * ROWS + rB] = cB;

        // warps 2-7: stage one uint4 of B(t+1) + sqC(t+1) into registers
        uint4 st0; float sqv = 0.f;
        if (pid >= 0 && t + 1 < NTIL) {
            const __nv_bfloat16* src = gb + (size_t)(t + 1) * NC * CDIM;
            { int q = pid, rr = q >> 3, g = q & 7; st0 = *(const uint4*)(src + (size_t)rr * CDIM + g * 8); }
            if (pid < 64) sqv = g_sqC[(size_t)b * NPTS + (t + 1) * NC + pid];
        }
        __syncthreads();   // pend + cnt visible; B(t) fully consumed

        if (tid < ROWS) {
            unsigned* lrow = list + tid * LSTR;
#pragma unroll
            for (int sg = 0; sg < 8; ++sg) {
                unsigned myc  = (unsigned)cnt[sg * ROWS + tid];
                unsigned cmax = __reduce_max_sync(0xffffffffu, myc);
                for (unsigned j = 0; j < cmax; ++j) {
                    unsigned kn = (j < myc) ? pend[(sg * 8 + (int)j) * ROWS + tid] : 0xFFFFFFFFu;
                    bool take = kn < worstm;
                    if (__any_sync(0xffffffffu, take)) {
                        if (take) lrow[wpos] = kn;           // 1 STS, dynamic slot
                        // rescan: slot-packed max via IMNMX
                        unsigned m = 0;
#pragma unroll
                        for (int s = 0; s < KSUP; s += 2) {
                            uint2 two = *(const uint2*)(lrow + s);
                            unsigned t0 = (two.x & 0xFFFFFFE0u) | (unsigned)s;
                            unsigned t1 = (two.y & 0xFFFFFFE0u) | (unsigned)(s + 1);
                            unsigned mx = t0 > t1 ? t0 : t1;
                            m = m > mx ? m : mx;
                        }
                        worstm = m;
                        wpos = (int)(m & 31u);
                    }
                }
            }
            thr[tid] = __uint_as_float(worstm | 0xFFFu);
        } else if (t + 1 < NTIL) {
            // warps 2-7: store staged uint4, then direct-load the rest
            const __nv_bfloat16* src = gb + (size_t)(t + 1) * NC * CDIM;
            { int q = pid, rr = q >> 3, g = q & 7; *(uint4*)(sm + SM_B0 + swz(rr, g)) = st0; }
            { int q = pid + 192, rr = q >> 3, g = q & 7;
              *(uint4*)(sm + SM_B0 + swz(rr, g)) = *(const uint4*)(src + (size_t)rr * CDIM + g * 8); }
            if (pid < 128) {
                int q = pid + 384, rr = q >> 3, g = q & 7;
                *(uint4*)(sm + SM_B0 + swz(rr, g)) = *(const uint4*)(src + (size_t)rr * CDIM + g * 8);
            }
            if (pid < 64) sqb[pid] = sqv;
        }
        __syncthreads();   // flush done (thr updated), B(t+1) ready, pend reusable
    }

    if (tid < ROWS) {
        short* op = g_cand + ((size_t)b * NPTS + row0 + tid) * KSUP;
        const unsigned* lrow = list + tid * LSTR;
#pragma unroll
        for (int k = 0; k < KSUP; ++k) op[k] = (short)(lrow[k] & 0xFFFu);
    }
}

// ---------------- kernel 2b: exact rescore (coalesced), top-16 ----------------
__global__ __launch_bounds__(256) void rescore_kernel() {
    __shared__ float xrow[8][CDIM];
    __shared__ float dots[8][KSUP];
    const int lane = threadIdx.x & 31;
    const int w    = threadIdx.x >> 5;
    const int b    = blockIdx.y;
    const int n    = blockIdx.x * 8 + w;
    const size_t rb = (size_t)b * NPTS + n;

    *(float2*)(&xrow[w][lane * 2]) = *(const float2*)(g_xt + rb * CDIM + lane * 2);
    __syncwarp();

    const short* cp = g_cand + rb * KSUP;
    const float* xseg = &xrow[w][(lane & 3) * 16];

    // 3 groups of 8 candidates; 4 lanes per candidate (coalesced 256B rows)
#pragma unroll
    for (int g = 0; g < 3; ++g) {
        int c = g * 8 + (lane >> 2);
        int j = (int)cp[c];
        const float* yp = g_xt + ((size_t)b * NPTS + j) * CDIM + (lane & 3) * 16;
        float d = 0.f;
#pragma unroll
        for (int q = 0; q < 4; ++q) {
            float4 yv = *(const float4*)(yp + q * 4);
            float4 xv = *(const float4*)(xseg + q * 4);
            d = fmaf(xv.x, yv.x, d);
            d = fmaf(xv.y, yv.y, d);
            d = fmaf(xv.z, yv.z, d);
            d = fmaf(xv.w, yv.w, d);
        }
        d += __shfl_xor_sync(0xffffffffu, d, 1);
        d += __shfl_xor_sync(0xffffffffu, d, 2);
        if ((lane & 3) == 0) dots[w][c] = d;
    }
    __syncwarp();

    ull key = ~0ULL;
    if (lane < KSUP) {
        int j = (int)cp[lane];
        if (j != n) {
            float dist = fmaf(-2.f, dots[w][lane], g_sq[(size_t)b * NPTS + j]);
            key = ((ull)fsort(dist) << 32) | (unsigned)j;
        }
    }
#pragma unroll
    for (int k = 2; k <= 32; k <<= 1) {
#pragma unroll
        for (int jj = k >> 1; jj > 0; jj >>= 1) {
            ull other = __shfl_xor_sync(0xffffffffu, key, jj);
            bool up   = ((lane & k) == 0);
            bool low  = ((lane & jj) == 0);
            bool keep_small = (low == up);
            ull mn = key < other ? key : other;
            ull mx = key < other ? other : key;
            key = keep_small ? mn : mx;
        }
    }
    if (lane < KNBR)
        g_idx[rb * KNBR + lane] = (int)(key & 0xFFFFu);
}

// ---------------- kernel 3: A = W1.x ; Cpre = (W2-W1).x + b1+b2 ----------------
__global__ void feat_kernel(const float* __restrict__ x,
                            const float* __restrict__ W1, const float* __restrict__ b1,
                            const float* __restrict__ W2, const float* __restrict__ b2) {
    __shared__ float xs [CDIM][64];
    __shared__ float w1s[COUT][CDIM];
    __shared__ float wds[COUT][CDIM];
    __shared__ float bs [COUT];

    const int tid = threadIdx.x;
    const int b   = blockIdx.y;
    const int n0  = blockIdx.x * 64;
    const float* xb = x + (size_t)b * CDIM * NPTS;

#pragma unroll
    for (int i = 0; i < 4; ++i) {
        int q = tid + i * 256, c = q >> 4, mg = q & 15;
        *(float4*)(&xs[c][mg * 4]) = *(const float4*)(xb + c * NPTS + n0 + mg * 4);
    }
#pragma unroll
    for (int i = 0; i < 4; ++i) {
        int q = tid + i * 256, o = q >> 4, cg = (q & 15) * 4;
        float4 w1v = *(const float4*)(W1 + o * CDIM + cg);
        float4 w2v = *(const float4*)(W2 + o * CDIM + cg);
        *(float4*)(&w1s[o][cg]) = w1v;
        *(float4*)(&wds[o][cg]) = make_float4(w2v.x - w1v.x, w2v.y - w1v.y,
                                              w2v.z - w1v.z, w2v.w - w1v.w);
    }
    if (tid < COUT) bs[tid] = b1[tid] + b2[tid];
    __syncthreads();

    const int tx = tid & 15;
    const int ty = tid >> 4;
    float aA[4][4] = {}, aC[4][4] = {};
#pragma unroll 16
    for (int c = 0; c < CDIM; ++c) {
        float4 xv = *(const float4*)(&xs[c][tx * 4]);
        float xr[4] = { xv.x, xv.y, xv.z, xv.w };
#pragma unroll
        for (int jj = 0; jj < 4; ++jj) {
            float w1e = w1s[ty * 4 + jj][c];
            float wde = wds[ty * 4 + jj][c];
#pragma unroll
            for (int i = 0; i < 4; ++i) {
                aA[i][jj] = fmaf(xr[i], w1e, aA[i][jj]);
                aC[i][jj] = fmaf(xr[i], wde, aC[i][jj]);
            }
        }
    }
#pragma unroll
    for (int i = 0; i < 4; ++i) {
        int n = n0 + tx * 4 + i;
        float* ap = g_A  + ((size_t)b * NPTS + n) * COUT + ty * 4;
        float* cp = g_Cp + ((size_t)b * NPTS + n) * COUT + ty * 4;
        *(float4*)ap = make_float4(aA[i][0], aA[i][1], aA[i][2], aA[i][3]);
        *(float4*)cp = make_float4(aC[i][0] + bs[ty * 4 + 0],
                                   aC[i][1] + bs[ty * 4 + 1],
                                   aC[i][2] + bs[ty * 4 + 2],
                                   aC[i][3] + bs[ty * 4 + 3]);
    }
}

// ---------------- kernel 4: gather-max + relu (2 points/thread ILP) ----------------
__global__ __launch_bounds__(256) void gather_kernel(float* __restrict__ out) {
    const int tid = threadIdx.x;
    const int b   = blockIdx.y;
    const int l   = tid & 63;
    const int g   = tid >> 6;
    const int n1  = blockIdx.x * 128 + l;
    const int n2  = n1 + 64;
    const int* ip1 = g_idx + ((size_t)b * NPTS + n1) * KNBR;
    const int* ip2 = g_idx + ((size_t)b * NPTS + n2) * KNBR;

    float mx1[16], mx2[16];
#pragma unroll
    for (int i = 0; i < 16; ++i) { mx1[i] = -3.4e38f; mx2[i] = -3.4e38f; }

#pragma unroll
    for (int k = 0; k < KNBR; ++k) {
        int j1 = ip1[k], j2 = ip2[k];
        const float4* ap1 = (const float4*)(g_A + ((size_t)b * NPTS + j1) * COUT + g * 16);
        const float4* ap2 = (const float4*)(g_A + ((size_t)b * NPTS + j2) * COUT + g * 16);
#pragma unroll
        for (int q = 0; q < 4; ++q) {
            float4 v1 = ap1[q];
            float4 v2 = ap2[q];
            mx1[q * 4 + 0] = fmaxf(mx1[q * 4 + 0], v1.x);
            mx1[q * 4 + 1] = fmaxf(mx1[q * 4 + 1], v1.y);
            mx1[q * 4 + 2] = fmaxf(mx1[q * 4 + 2], v1.z);
            mx1[q * 4 + 3] = fmaxf(mx1[q * 4 + 3], v1.w);
            mx2[q * 4 + 0] = fmaxf(mx2[q * 4 + 0], v2.x);
            mx2[q * 4 + 1] = fmaxf(mx2[q * 4 + 1], v2.y);
            mx2[q * 4 + 2] = fmaxf(mx2[q * 4 + 2], v2.z);
            mx2[q * 4 + 3] = fmaxf(mx2[q * 4 + 3], v2.w);
        }
    }
    const float4* cp1 = (const float4*)(g_Cp + ((size_t)b * NPTS + n1) * COUT + g * 16);
    const float4* cp2 = (const float4*)(g_Cp + ((size_t)b * NPTS + n2) * COUT + g * 16);
    float* op1 = out + ((size_t)b * COUT + g * 16) * NPTS + n1;
    float* op2 = out + ((size_t)b * COUT + g * 16) * NPTS + n2;
#pragma unroll
    for (int q = 0; q < 4; ++q) {
        float4 c1 = cp1[q];
        float4 c2 = cp2[q];
        op1[(q * 4 + 0) * NPTS] = fmaxf(c1.x + mx1[q * 4 + 0], 0.f);
        op1[(q * 4 + 1) * NPTS] = fmaxf(c1.y + mx1[q * 4 + 1], 0.f);
        op1[(q * 4 + 2) * NPTS] = fmaxf(c1.z + mx1[q * 4 + 2], 0.f);
        op1[(q * 4 + 3) * NPTS] = fmaxf(c1.w + mx1[q * 4 + 3], 0.f);
        op2[(q * 4 + 0) * NPTS] = fmaxf(c2.x + mx2[q * 4 + 0], 0.f);
        op2[(q * 4 + 1) * NPTS] = fmaxf(c2.y + mx2[q * 4 + 1], 0.f);
        op2[(q * 4 + 2) * NPTS] = fmaxf(c2.z + mx2[q * 4 + 2], 0.f);
        op2[(q * 4 + 3) * NPTS] = fmaxf(c2.w + mx2[q * 4 + 3], 0.f);
    }
}

// ---------------- launch ----------------
extern "C" void kernel_launch(void* const* d_in, const int* in_sizes, int n_in,
                              void* d_out, int out_size) {
    const float *x = nullptr, *W1 = nullptr, *b1 = nullptr, *W2 = nullptr, *b2 = nullptr;
    for (int i = 0; i < n_in; ++i) {
        int s = in_sizes[i];
        const float* p = (const float*)d_in[i];
        if      (s == BATCH * CDIM * NPTS) x = p;
        else if (s == COUT * CDIM)        { if (!W1) W1 = p; else W2 = p; }
        else if (s == COUT)               { if (!b1) b1 = p; else b2 = p; }
    }
    float* out = (float*)d_out;
    (void)out_size;

    cudaFuncSetAttribute(knn_mma_kernel, cudaFuncAttributeMaxDynamicSharedMemorySize, KNN_SMEM);

    // knn placed 4th so the fixed ncu capture slot profiles it
    sq_kernel      <<<dim3(NPTS / 256, BATCH), 256>>>(x);
    tr_kernel      <<<dim3(NPTS / 32, CDIM / 32, BATCH), dim3(32, 8)>>>(x);
    feat_kernel    <<<dim3(NPTS / 64, BATCH), 256>>>(x, W1, b1, W2, b2);
    knn_mma_kernel <<<dim3(NPTS / ROWS, BATCH), 256, KNN_SMEM>>>();
    rescore_kernel <<<dim3(NPTS / 8, BATCH), 256>>>();
    gather_kernel  <<<dim3(NPTS / 128, BATCH), 256>>>(out);
}

// round 16
// speedup vs baseline: 1.3739x; 1.2796x over previous
#include <cuda_runtime.h>
#include <cuda_bf16.h>
#include <cstdint>

#define BATCH 8
#define CDIM  64
#define NPTS  4096
#define KNBR  16
#define COUT  64
#define KSUP  24          // candidate superset per row (6 groups of 4)
#define LSTR  26          // smem list row stride (words, EVEN: keeps LDS.64 aligned)
#define NC    64          // candidates per tile in phase B
#define NTIL  (NPTS / NC) // 64
#define COFF  512.0f      // row-order-preserving positive offset

typedef unsigned long long ull;

// ---------------- scratch (no allocations allowed) ----------------
__device__ float          g_sq  [BATCH * NPTS];
__device__ float          g_sqC [BATCH * NPTS];          // sq + COFF
__device__ int            g_idx [BATCH * NPTS * KNBR];
__device__ float          g_A   [BATCH * NPTS * COUT];
__device__ float          g_Cp  [BATCH * NPTS * COUT];
__device__ float          g_xt  [BATCH * NPTS * CDIM];   // point-major fp32
__device__ __nv_bfloat16  g_xh  [BATCH * NPTS * CDIM];   // point-major bf16
__device__ short          g_cand[BATCH * NPTS * KSUP];

// ---------------- helpers ----------------
__device__ __forceinline__ uint32_t smem_u32(const void* p) {
    uint32_t a;
    asm("{ .reg .u64 t; cvta.to.shared.u64 t, %1; cvt.u32.u64 %0, t; }" : "=r"(a) : "l"(p));
    return a;
}
__device__ __forceinline__ unsigned fsort(float v) {
    unsigned u = __float_as_uint(v);
    return u ^ (0x80000000u | (unsigned)((int)u >> 31));
}
__device__ __forceinline__ void ldmx4(uint32_t* r, uint32_t addr) {
    asm volatile("ldmatrix.sync.aligned.m8n8.x4.shared.b16 {%0,%1,%2,%3}, [%4];"
                 : "=r"(r[0]), "=r"(r[1]), "=r"(r[2]), "=r"(r[3]) : "r"(addr));
}
__device__ __forceinline__ void mma16816(float* c, const uint32_t* a, uint32_t b0, uint32_t b1) {
    asm volatile("mma.sync.aligned.m16n8k16.row.col.f32.bf16.bf16.f32 "
                 "{%0,%1,%2,%3}, {%4,%5,%6,%7}, {%8,%9}, {%0,%1,%2,%3};"
                 : "+f"(c[0]), "+f"(c[1]), "+f"(c[2]), "+f"(c[3])
                 : "r"(a[0]), "r"(a[1]), "r"(a[2]), "r"(a[3]), "r"(b0), "r"(b1));
}
// swizzled byte offset of 16B granule g (0..7) in row rr of a [rows][64bf16] tile
__device__ __forceinline__ int swz(int rr, int g) {
    return rr * 128 + ((g ^ (rr & 7)) << 4);
}

// ---------------- kernel 1: squared norms (exact fp32) ----------------
__global__ void sq_kernel(const float* __restrict__ x) {
    int b = blockIdx.y;
    int n = blockIdx.x * blockDim.x + threadIdx.x;
    const float* xp = x + (size_t)b * CDIM * NPTS + n;
    float s = 0.f;
#pragma unroll
    for (int c = 0; c < CDIM; ++c) { float v = xp[c * NPTS]; s = fmaf(v, v, s); }
    g_sq [b * NPTS + n] = s;
    g_sqC[b * NPTS + n] = s + COFF;
}

// ---------------- kernel 1b: transpose to point-major fp32 + bf16 ----------------
__global__ void tr_kernel(const float* __restrict__ x) {
    __shared__ float tile[32][33];
    const int tx = threadIdx.x, ty = threadIdx.y;
    const int n0 = blockIdx.x * 32, c0 = blockIdx.y * 32, b = blockIdx.z;
    const float* xb = x + (size_t)b * CDIM * NPTS;
#pragma unroll
    for (int i = 0; i < 4; ++i)
        tile[ty + i * 8][tx] = xb[(c0 + ty + i * 8) * NPTS + n0 + tx];
    __syncthreads();
#pragma unroll
    for (int i = 0; i < 4; ++i) {
        int n = n0 + ty + i * 8, c = c0 + tx;
        float v = tile[tx][ty + i * 8];
        size_t o = ((size_t)b * NPTS + n) * CDIM + c;
        g_xt[o] = v;
        g_xh[o] = __float2bfloat16(v);
    }
}

// ---------------- kernel 2: HMMA approx distances + top-24 superset ----------------
// r13 structure (128 rows, grid 256). Keys: raw fp32 bits of v = sqC[m]-2*dot.
// key = (bits & 0xFFFFF000) | idx12. Flush insert uses hierarchical group-max:
// 6 register-resident group maxima (slot-mangled), reload only the touched
// group from smem -> ~18 ops/insert vs 47 for the flat rescan.
#define SM_A    0                            // 16384
#define SM_B0   16384                        // 8192
#define SM_SQ   24576                        // float[2][64] = 512 (only 256 used/buf)
#define SM_THR  24832                        // float[128] = 512
#define SM_CNT  25344                        // int[4][128] = 2048
#define SM_PEND 27392                        // u32[4][16][128] = 32768
#define SM_LIST 60160                        // u32[128][LSTR] = 13312
#define KNN_SMEM (SM_LIST + 128 * LSTR * 4)  // 73472

__global__ __launch_bounds__(256, 3) void knn_mma_kernel() {
    extern __shared__ char sm[];
    float*    sqb  = (float*)   (sm + SM_SQ);
    float*    thr  = (float*)   (sm + SM_THR);
    int*      cnt  = (int*)     (sm + SM_CNT);
    unsigned* pend = (unsigned*)(sm + SM_PEND);
    unsigned* list = (unsigned*)(sm + SM_LIST);

    const int tid  = threadIdx.x;
    const int w    = tid >> 5;
    const int lane = tid & 31;
    const int b    = blockIdx.y;
    const int row0 = blockIdx.x * 128;
    const uint32_t smb = smem_u32(sm);

    const __nv_bfloat16* gb = g_xh + (size_t)b * NPTS * CDIM;

    // prologue: A tile (swizzled), B tile 0, sqC slice 0, thr, list init
#pragma unroll
    for (int i = 0; i < 4; ++i) {    // A: 1024 uint4
        int q = tid + i * 256, rr = q >> 3, g = q & 7;
        *(uint4*)(sm + SM_A + swz(rr, g)) = *(const uint4*)(gb + (size_t)(row0 + rr) * CDIM + g * 8);
    }
#pragma unroll
    for (int i = 0; i < 2; ++i) {    // B0: 512 uint4 (64 rows)
        int q = tid + i * 256, rr = q >> 3, g = q & 7;
        *(uint4*)(sm + SM_B0 + swz(rr, g)) = *(const uint4*)(gb + (size_t)rr * CDIM + g * 8);
    }
    if (tid < 16)
        *(float4*)(sqb + tid * 4) = *(const float4*)(g_sqC + (size_t)b * NPTS + tid * 4);
    if (tid < 128) thr[tid] = 3.4e38f;
    for (int i = tid; i < 128 * LSTR; i += 256) list[i] = 0xFFFFFFFFu;
    __syncthreads();

    // GEMM role (all 8 warps): rows wrow..wrow+15
    const int wrow = w * 16;
    const int arow = wrow + (lane & 7) + ((lane >> 3) & 1) * 8;
    const int rA   = wrow + (lane >> 2);
    const int rB   = rA + 8;
    const int seg  = lane & 3;
    const int mloc = seg * 2;
    const int t2   = tid - 128;

    // A fragments: block-constant, load once
    uint32_t af[4][4];
#pragma unroll
    for (int kc = 0; kc < 4; ++kc) {
        int ach = kc * 2 + (lane >> 4);
        ldmx4(af[kc], smb + SM_A + swz(arow, ach));
    }

    // selection state (threads 0..127 own row = row0 + tid); list in smem;
    // gm[g] = slot-mangled max of group g (key & ~31 | slot)
    unsigned gm[6];
#pragma unroll
    for (int i = 0; i < 6; ++i) gm[i] = 0xFFFFFFE0u | (unsigned)(i * 4 + 3);
    unsigned worstm = 0xFFFFFFE0u | 23u;
    int wpos = 23;

    for (int t = 0; t < NTIL; ++t) {
        const float thrA = thr[rA];
        const float thrB = thr[rB];
        const int   tb   = t * NC;
        int cA = 0, cB = 0;   // register counters; <=16 by construction

#pragma unroll
        for (int nf = 0; nf < 8; ++nf) {
            int brow = nf * 8 + (lane & 7);
            int bg   = lane >> 3;
            uint32_t p[4], q4[4];
            ldmx4(p,  smb + SM_B0 + swz(brow, bg));
            ldmx4(q4, smb + SM_B0 + swz(brow, bg + 4));
            float acc[4] = {0.f, 0.f, 0.f, 0.f};
            mma16816(acc, af[0], p[0],  p[1]);
            mma16816(acc, af[1], p[2],  p[3]);
            mma16816(acc, af[2], q4[0], q4[1]);
            mma16816(acc, af[3], q4[2], q4[3]);

            // fused epilogue: v = sqC[m] - 2*dot  (>0; per-row order == d^2)
            int    ml = mloc + nf * 8;
            float2 ss = *(const float2*)(sqb + ml);
            int    m0 = tb + ml;
            float v00 = fmaf(-2.f, acc[0], ss.x);
            float v01 = fmaf(-2.f, acc[1], ss.y);
            float v10 = fmaf(-2.f, acc[2], ss.x);
            float v11 = fmaf(-2.f, acc[3], ss.y);
            if (v00 <= thrA) pend[(seg * 16 + cA++) * 128 + rA] = (__float_as_uint(v00) & 0xFFFFF000u) | (unsigned)m0;
            if (v01 <= thrA) pend[(seg * 16 + cA++) * 128 + rA] = (__float_as_uint(v01) & 0xFFFFF000u) | (unsigned)(m0 + 1);
            if (v10 <= thrB) pend[(seg * 16 + cB++) * 128 + rB] = (__float_as_uint(v10) & 0xFFFFF000u) | (unsigned)m0;
            if (v11 <= thrB) pend[(seg * 16 + cB++) * 128 + rB] = (__float_as_uint(v11) & 0xFFFFF000u) | (unsigned)(m0 + 1);
        }
        cnt[seg * 128 + rA] = cA;
        cnt[seg * 128 + rB] = cB;

        // warps 4-7: stage first half of B(t+1) + sqC(t+1) into registers
        uint4 st0, st1; float sqv = 0.f;
        if (tid >= 128 && t + 1 < NTIL) {
            const __nv_bfloat16* src = gb + (size_t)(t + 1) * NC * CDIM;
            { int q = t2,       rr = q >> 3, g = q & 7; st0 = *(const uint4*)(src + (size_t)rr * CDIM + g * 8); }
            { int q = t2 + 128, rr = q >> 3, g = q & 7; st1 = *(const uint4*)(src + (size_t)rr * CDIM + g * 8); }
            if (t2 < 64) sqv = g_sqC[(size_t)b * NPTS + (t + 1) * NC + t2];
        }
        __syncthreads();   // pend + cnt visible; B(t) fully consumed

        if (tid < 128) {
            unsigned* lrow = list + tid * LSTR;
#pragma unroll
            for (int sg = 0; sg < 4; ++sg) {
                unsigned myc  = (unsigned)cnt[sg * 128 + tid];
                unsigned cmax = __reduce_max_sync(0xffffffffu, myc);
                for (unsigned j = 0; j < cmax; ++j) {
                    unsigned kn = (j < myc) ? pend[(sg * 16 + (int)j) * 128 + tid] : 0xFFFFFFFFu;
                    if (kn < worstm) {
                        lrow[wpos] = kn;                      // 1 STS, dynamic slot
                        int grp  = wpos >> 2;
                        int base = grp << 2;
                        uint2 a2 = *(const uint2*)(lrow + base);
                        uint2 b2 = *(const uint2*)(lrow + base + 2);
                        unsigned m0 = (a2.x & 0xFFFFFFE0u) | (unsigned)base;
                        unsigned m1 = (a2.y & 0xFFFFFFE0u) | (unsigned)(base + 1);
                        unsigned m2 = (b2.x & 0xFFFFFFE0u) | (unsigned)(base + 2);
                        unsigned m3 = (b2.y & 0xFFFFFFE0u) | (unsigned)(base + 3);
                        unsigned gmax = m0 > m1 ? m0 : m1;
                        unsigned g2   = m2 > m3 ? m2 : m3;
                        gmax = gmax > g2 ? gmax : g2;
#pragma unroll
                        for (int i = 0; i < 6; ++i)
                            if (i == grp) gm[i] = gmax;
                        unsigned w01 = gm[0] > gm[1] ? gm[0] : gm[1];
                        unsigned w23 = gm[2] > gm[3] ? gm[2] : gm[3];
                        unsigned w45 = gm[4] > gm[5] ? gm[4] : gm[5];
                        unsigned wv  = w01 > w23 ? w01 : w23;
                        wv = wv > w45 ? wv : w45;
                        worstm = wv;
                        wpos   = (int)(wv & 31u);
                    }
                }
            }
            thr[tid] = __uint_as_float(worstm | 0xFFFu);
        } else if (t + 1 < NTIL) {
            // warps 4-7: store staged half, then load+store second half
            const __nv_bfloat16* src = gb + (size_t)(t + 1) * NC * CDIM;
            { int q = t2,       rr = q >> 3, g = q & 7; *(uint4*)(sm + SM_B0 + swz(rr, g)) = st0; }
            { int q = t2 + 128, rr = q >> 3, g = q & 7; *(uint4*)(sm + SM_B0 + swz(rr, g)) = st1; }
            { int q = t2 + 256, rr = q >> 3, g = q & 7;
              *(uint4*)(sm + SM_B0 + swz(rr, g)) = *(const uint4*)(src + (size_t)rr * CDIM + g * 8); }
            { int q = t2 + 384, rr = q >> 3, g = q & 7;
              *(uint4*)(sm + SM_B0 + swz(rr, g)) = *(const uint4*)(src + (size_t)rr * CDIM + g * 8); }
            if (t2 < 64) sqb[t2] = sqv;
        }
        __syncthreads();   // flush done (thr updated), B(t+1) ready, pend reusable
    }

    if (tid < 128) {
        short* op = g_cand + ((size_t)b * NPTS + row0 + tid) * KSUP;
        const unsigned* lrow = list + tid * LSTR;
#pragma unroll
        for (int k = 0; k < KSUP; ++k) op[k] = (short)(lrow[k] & 0xFFFu);
    }
}

// ---------------- kernel 2b: exact rescore (coalesced), top-16 ----------------
__global__ __launch_bounds__(256) void rescore_kernel() {
    __shared__ float xrow[8][CDIM];
    __shared__ float dots[8][KSUP];
    const int lane = threadIdx.x & 31;
    const int w    = threadIdx.x >> 5;
    const int b    = blockIdx.y;
    const int n    = blockIdx.x * 8 + w;
    const size_t rb = (size_t)b * NPTS + n;

    *(float2*)(&xrow[w][lane * 2]) = *(const float2*)(g_xt + rb * CDIM + lane * 2);
    __syncwarp();

    const short* cp = g_cand + rb * KSUP;
    const float* xseg = &xrow[w][(lane & 3) * 16];

    // 3 groups of 8 candidates; 4 lanes per candidate (coalesced 256B rows)
#pragma unroll
    for (int g = 0; g < 3; ++g) {
        int c = g * 8 + (lane >> 2);
        int j = (int)cp[c];
        const float* yp = g_xt + ((size_t)b * NPTS + j) * CDIM + (lane & 3) * 16;
        float d = 0.f;
#pragma unroll
        for (int q = 0; q < 4; ++q) {
            float4 yv = *(const float4*)(yp + q * 4);
            float4 xv = *(const float4*)(xseg + q * 4);
            d = fmaf(xv.x, yv.x, d);
            d = fmaf(xv.y, yv.y, d);
            d = fmaf(xv.z, yv.z, d);
            d = fmaf(xv.w, yv.w, d);
        }
        d += __shfl_xor_sync(0xffffffffu, d, 1);
        d += __shfl_xor_sync(0xffffffffu, d, 2);
        if ((lane & 3) == 0) dots[w][c] = d;
    }
    __syncwarp();

    ull key = ~0ULL;
    if (lane < KSUP) {
        int j = (int)cp[lane];
        if (j != n) {
            float dist = fmaf(-2.f, dots[w][lane], g_sq[(size_t)b * NPTS + j]);
            key = ((ull)fsort(dist) << 32) | (unsigned)j;
        }
    }
#pragma unroll
    for (int k = 2; k <= 32; k <<= 1) {
#pragma unroll
        for (int jj = k >> 1; jj > 0; jj >>= 1) {
            ull other = __shfl_xor_sync(0xffffffffu, key, jj);
            bool up   = ((lane & k) == 0);
            bool low  = ((lane & jj) == 0);
            bool keep_small = (low == up);
            ull mn = key < other ? key : other;
            ull mx = key < other ? other : key;
            key = keep_small ? mn : mx;
        }
    }
    if (lane < KNBR)
        g_idx[rb * KNBR + lane] = (int)(key & 0xFFFFu);
}

// ---------------- kernel 3: A = W1.x ; Cpre = (W2-W1).x + b1+b2 ----------------
__global__ void feat_kernel(const float* __restrict__ x,
                            const float* __restrict__ W1, const float* __restrict__ b1,
                            const float* __restrict__ W2, const float* __restrict__ b2) {
    __shared__ float xs [CDIM][64];
    __shared__ float w1s[COUT][CDIM];
    __shared__ float wds[COUT][CDIM];
    __shared__ float bs [COUT];

    const int tid = threadIdx.x;
    const int b   = blockIdx.y;
    const int n0  = blockIdx.x * 64;
    const float* xb = x + (size_t)b * CDIM * NPTS;

#pragma unroll
    for (int i = 0; i < 4; ++i) {
        int q = tid + i * 256, c = q >> 4, mg = q & 15;
        *(float4*)(&xs[c][mg * 4]) = *(const float4*)(xb + c * NPTS + n0 + mg * 4);
    }
#pragma unroll
    for (int i = 0; i < 4; ++i) {
        int q = tid + i * 256, o = q >> 4, cg = (q & 15) * 4;
        float4 w1v = *(const float4*)(W1 + o * CDIM + cg);
        float4 w2v = *(const float4*)(W2 + o * CDIM + cg);
        *(float4*)(&w1s[o][cg]) = w1v;
        *(float4*)(&wds[o][cg]) = make_float4(w2v.x - w1v.x, w2v.y - w1v.y,
                                              w2v.z - w1v.z, w2v.w - w1v.w);
    }
    if (tid < COUT) bs[tid] = b1[tid] + b2[tid];
    __syncthreads();

    const int tx = tid & 15;
    const int ty = tid >> 4;
    float aA[4][4] = {}, aC[4][4] = {};
#pragma unroll 16
    for (int c = 0; c < CDIM; ++c) {
        float4 xv = *(const float4*)(&xs[c][tx * 4]);
        float xr[4] = { xv.x, xv.y, xv.z, xv.w };
#pragma unroll
        for (int jj = 0; jj < 4; ++jj) {
            float w1e = w1s[ty * 4 + jj][c];
            float wde = wds[ty * 4 + jj][c];
#pragma unroll
            for (int i = 0; i < 4; ++i) {
                aA[i][jj] = fmaf(xr[i], w1e, aA[i][jj]);
                aC[i][jj] = fmaf(xr[i], wde, aC[i][jj]);
            }
        }
    }
#pragma unroll
    for (int i = 0; i < 4; ++i) {
        int n = n0 + tx * 4 + i;
        float* ap = g_A  + ((size_t)b * NPTS + n) * COUT + ty * 4;
        float* cp = g_Cp + ((size_t)b * NPTS + n) * COUT + ty * 4;
        *(float4*)ap = make_float4(aA[i][0], aA[i][1], aA[i][2], aA[i][3]);
        *(float4*)cp = make_float4(aC[i][0] + bs[ty * 4 + 0],
                                   aC[i][1] + bs[ty * 4 + 1],
                                   aC[i][2] + bs[ty * 4 + 2],
                                   aC[i][3] + bs[ty * 4 + 3]);
    }
}

// ---------------- kernel 4: gather-max + relu (2 points/thread ILP) ----------------
__global__ __launch_bounds__(256) void gather_kernel(float* __restrict__ out) {
    const int tid = threadIdx.x;
    const int b   = blockIdx.y;
    const int l   = tid & 63;
    const int g   = tid >> 6;
    const int n1  = blockIdx.x * 128 + l;
    const int n2  = n1 + 64;
    const int* ip1 = g_idx + ((size_t)b * NPTS + n1) * KNBR;
    const int* ip2 = g_idx + ((size_t)b * NPTS + n2) * KNBR;

    float mx1[16], mx2[16];
#pragma unroll
    for (int i = 0; i < 16; ++i) { mx1[i] = -3.4e38f; mx2[i] = -3.4e38f; }

#pragma unroll
    for (int k = 0; k < KNBR; ++k) {
        int j1 = ip1[k], j2 = ip2[k];
        const float4* ap1 = (const float4*)(g_A + ((size_t)b * NPTS + j1) * COUT + g * 16);
        const float4* ap2 = (const float4*)(g_A + ((size_t)b * NPTS + j2) * COUT + g * 16);
#pragma unroll
        for (int q = 0; q < 4; ++q) {
            float4 v1 = ap1[q];
            float4 v2 = ap2[q];
            mx1[q * 4 + 0] = fmaxf(mx1[q * 4 + 0], v1.x);
            mx1[q * 4 + 1] = fmaxf(mx1[q * 4 + 1], v1.y);
            mx1[q * 4 + 2] = fmaxf(mx1[q * 4 + 2], v1.z);
            mx1[q * 4 + 3] = fmaxf(mx1[q * 4 + 3], v1.w);
            mx2[q * 4 + 0] = fmaxf(mx2[q * 4 + 0], v2.x);
            mx2[q * 4 + 1] = fmaxf(mx2[q * 4 + 1], v2.y);
            mx2[q * 4 + 2] = fmaxf(mx2[q * 4 + 2], v2.z);
            mx2[q * 4 + 3] = fmaxf(mx2[q * 4 + 3], v2.w);
        }
    }
    const float4* cp1 = (const float4*)(g_Cp + ((size_t)b * NPTS + n1) * COUT + g * 16);
    const float4* cp2 = (const float4*)(g_Cp + ((size_t)b * NPTS + n2) * COUT + g * 16);
    float* op1 = out + ((size_t)b * COUT + g * 16) * NPTS + n1;
    float* op2 = out + ((size_t)b * COUT + g * 16) * NPTS + n2;
#pragma unroll
    for (int q = 0; q < 4; ++q) {
        float4 c1 = cp1[q];
        float4 c2 = cp2[q];
        op1[(q * 4 + 0) * NPTS] = fmaxf(c1.x + mx1[q * 4 + 0], 0.f);
        op1[(q * 4 + 1) * NPTS] = fmaxf(c1.y + mx1[q * 4 + 1], 0.f);
        op1[(q * 4 + 2) * NPTS] = fmaxf(c1.z + mx1[q * 4 + 2], 0.f);
        op1[(q * 4 + 3) * NPTS] = fmaxf(c1.w + mx1[q * 4 + 3], 0.f);
        op2[(q * 4 + 0) * NPTS] = fmaxf(c2.x + mx2[q * 4 + 0], 0.f);
        op2[(q * 4 + 1) * NPTS] = fmaxf(c2.y + mx2[q * 4 + 1], 0.f);
        op2[(q * 4 + 2) * NPTS] = fmaxf(c2.z + mx2[q * 4 + 2], 0.f);
        op2[(q * 4 + 3) * NPTS] = fmaxf(c2.w + mx2[q * 4 + 3], 0.f);
    }
}

// ---------------- launch ----------------
extern "C" void kernel_launch(void* const* d_in, const int* in_sizes, int n_in,
                              void* d_out, int out_size) {
    const float *x = nullptr, *W1 = nullptr, *b1 = nullptr, *W2 = nullptr, *b2 = nullptr;
    for (int i = 0; i < n_in; ++i) {
        int s = in_sizes[i];
        const float* p = (const float*)d_in[i];
        if      (s == BATCH * CDIM * NPTS) x = p;
        else if (s == COUT * CDIM)        { if (!W1) W1 = p; else W2 = p; }
        else if (s == COUT)               { if (!b1) b1 = p; else b2 = p; }
    }
    float* out = (float*)d_out;
    (void)out_size;

    cudaFuncSetAttribute(knn_mma_kernel, cudaFuncAttributeMaxDynamicSharedMemorySize, KNN_SMEM);

    // knn placed 4th so the fixed ncu capture slot profiles it
    sq_kernel      <<<dim3(NPTS / 256, BATCH), 256>>>(x);
    tr_kernel      <<<dim3(NPTS / 32, CDIM / 32, BATCH), dim3(32, 8)>>>(x);
    feat_kernel    <<<dim3(NPTS / 64, BATCH), 256>>>(x, W1, b1, W2, b2);
    knn_mma_kernel <<<dim3(NPTS / 128, BATCH), 256, KNN_SMEM>>>();
    rescore_kernel <<<dim3(NPTS / 8, BATCH), 256>>>();
    gather_kernel  <<<dim3(NPTS / 128, BATCH), 256>>>(out);
}